// round 9
// baseline (speedup 1.0000x reference)
#include <cuda_runtime.h>
#include <cuda_bf16.h>
#include <cstdint>

// AddingGaussianBlur: x (64,512,512,3) f32, stds (64,) f32 -> out f32.
//
// Separable (reference's 3x3 kernel depends only on column index):
//   vertical  : unweighted 3-row sum (zero padded)
//   horizontal: [a, 1, a] / (3*(1+2a)),  a = exp(-1/s^2), s = 3*std[b]
//
// R9 = R7 (cp.async row ring, thread-private; register vertical window; smem
// vsum exchange; 1 row/iter) with two deltas:
//   - cp.async.cg: read-once input bypasses L1
//   - __launch_bounds__(384, 5): squeeze 35 -> 34 regs so 5 blocks/SM
//     co-reside (60 warps, 93.75% theoretical occupancy). Safe here because
//     MLP lives in the cp.async ring, not in registers (unlike R6).

#define H       512
#define ROWW    1536            // 512 * 3 floats per image row
#define NT      384             // 384 threads x float4 = one row
#define RPB     32              // rows per block band
#define DEP     3               // rows in flight
#define NSLOT   4               // ring slots (power of 2)
#define PAD     4               // float halo each side of vsum row
#define SROW    (ROWW + 2 * PAD)

__global__ __launch_bounds__(NT, 5)
void gauss_blur_kernel(const float* __restrict__ x,
                       const float* __restrict__ stds,
                       float* __restrict__ out)
{
    __shared__ __align__(16) float ring[NSLOT][ROWW];
    __shared__ __align__(16) float vs[2][SROW];

    const int b  = blockIdx.y;
    const int i0 = blockIdx.x * RPB;
    const int t  = threadIdx.x;

    // zero vsum halos once (visible after first __syncthreads)
    if (t < 8) {
        const int buf = t >> 2, idx = t & 3;
        vs[buf][idx] = 0.0f;
        vs[buf][ROWW + PAD + idx] = 0.0f;
    }

    const float s   = stds[b] * 3.0f;
    const float a   = expf(-1.0f / (s * s));
    const float inv = 1.0f / (3.0f * (1.0f + 2.0f * a));

    const float* __restrict__ xb = x   + (size_t)b * H * ROWW;
    float*       __restrict__ ob = out + (size_t)b * H * ROWW;

    const uint32_t ring_smem = (uint32_t)__cvta_generic_to_shared(&ring[0][0]) + t * 16u;
    const float4 Z = make_float4(0.0f, 0.0f, 0.0f, 0.0f);

    // Issue one row into the ring: cp.async.cg if in range, STS zeros
    // otherwise. Always commits a group so wait_group counts stay static.
    auto issue = [&](int gi) {
        const int slot = (gi - i0 + 1) & (NSLOT - 1);
        if ((unsigned)gi < (unsigned)H) {
            const float* src = xb + (size_t)gi * ROWW + t * 4;
            const uint32_t dst = ring_smem + slot * (ROWW * 4);
            asm volatile("cp.async.cg.shared.global [%0], [%1], 16;\n"
                         :: "r"(dst), "l"(src));
        } else {
            reinterpret_cast<float4*>(ring[slot] + t * 4)[0] = Z;
        }
        asm volatile("cp.async.commit_group;\n");
    };

    // Prologue: rows i0-1 .. i0+2 (4 groups), drain to 2 pending so rows
    // i0-1 and i0 are resident.
    issue(i0 - 1);
    issue(i0);
    issue(i0 + 1);
    issue(i0 + 2);
    asm volatile("cp.async.wait_group 2;\n");

    float4 rm = reinterpret_cast<const float4*>(ring[0] + t * 4)[0];  // row i0-1
    float4 rc = reinterpret_cast<const float4*>(ring[1] + t * 4)[0];  // row i0

    int par = 0;
    #pragma unroll 1
    for (int r = 0; r < RPB; r++) {
        const int gi = i0 + r;

        // keep DEP rows in flight
        issue(gi + DEP);
        // rows <= gi+1 complete (pending: gi+2, gi+3)
        asm volatile("cp.async.wait_group 2;\n");

        const int slot = (r + 2) & (NSLOT - 1);   // row gi+1
        const float4 rp = reinterpret_cast<const float4*>(ring[slot] + t * 4)[0];

        // vertical sum
        float4 v;
        v.x = rm.x + rc.x + rp.x;
        v.y = rm.y + rc.y + rp.y;
        v.z = rm.z + rc.z + rp.z;
        v.w = rm.w + rc.w + rp.w;

        float* sv = vs[par];
        reinterpret_cast<float4*>(sv + PAD)[t] = v;
        __syncthreads();

        // neighbor chunks (16B aligned): L = vsum[4t-4..4t-1], R = vsum[4t+4..4t+7]
        const float4 L = reinterpret_cast<const float4*>(sv)[t];
        const float4 R = reinterpret_cast<const float4*>(sv + PAD + 4)[t];

        // out[e] = inv * (a*(vsum[e-3] + vsum[e+3]) + vsum[e]),  e = 4t+j
        float4 o;
        o.x = inv * (a * (L.y + v.w) + v.x);
        o.y = inv * (a * (L.z + R.x) + v.y);
        o.z = inv * (a * (L.w + R.y) + v.z);
        o.w = inv * (a * (v.x + R.z) + v.w);

        __stcs(&reinterpret_cast<float4*>(ob + (size_t)gi * ROWW)[t], o);

        // rotate window; flip vsum buffer (reuse of vs[par] two iterations
        // later is ordered by the interleaving __syncthreads)
        rm = rc; rc = rp;
        par ^= 1;
    }
}

extern "C" void kernel_launch(void* const* d_in, const int* in_sizes, int n_in,
                              void* d_out, int out_size)
{
    const float* x    = (const float*)d_in[0];
    const float* stds = (const float*)d_in[1];
    float* out        = (float*)d_out;

    dim3 grid(H / RPB, 64);   // (16, 64) = 1024 blocks
    gauss_blur_kernel<<<grid, NT>>>(x, stds, out);
}

// round 10
// speedup vs baseline: 1.0885x; 1.0885x over previous
#include <cuda_runtime.h>
#include <cuda_bf16.h>
#include <cstdint>

// AddingGaussianBlur: x (64,512,512,3) f32, stds (64,) f32 -> out f32.
//
// Separable (reference's 3x3 kernel depends only on column index):
//   out = inv * sum_{3 rows} h(row),  h[e] = a*(x[e-3]+x[e+3]) + x[e]
//   a = exp(-1/s^2), s = 3*std[b], inv = 1/(3*(1+2a))
//
// R10: horizontal-first. cp.async.cg streams rows into an 8-slot smem ring;
// after wait+bar each thread reads chunks t-1,t,t+1 of the NEW row directly
// from the ring (3 independent LDS.128), computes h in registers, and rolls
// hm/hc/hp. No vsum exchange arrays, no mid-chain STS->bar->LDS stage: the
// single barrier per row sits right after wait_group (it is also the
// cross-thread visibility fence the ring needs). ~6 rows in flight.

#define H       512
#define ROWW    1536            // 512 * 3 floats per image row
#define NCH     384             // float4 chunks per row
#define NT      384             // one thread per chunk
#define RPB     32              // rows per block band
#define NSLOT   8               // ring slots (power of 2) -> 48KB smem

__global__ __launch_bounds__(NT)
void gauss_blur_kernel(const float* __restrict__ x,
                       const float* __restrict__ stds,
                       float* __restrict__ out)
{
    __shared__ __align__(16) float ring[NSLOT][ROWW];

    const int b  = blockIdx.y;
    const int i0 = blockIdx.x * RPB;
    const int t  = threadIdx.x;

    const float s   = stds[b] * 3.0f;
    const float a   = expf(-1.0f / (s * s));
    const float inv = 1.0f / (3.0f * (1.0f + 2.0f * a));

    const float* __restrict__ xb = x   + (size_t)b * H * ROWW;
    float*       __restrict__ ob = out + (size_t)b * H * ROWW;

    const uint32_t ring_smem = (uint32_t)__cvta_generic_to_shared(&ring[0][0]) + t * 16u;
    const float4 Z = make_float4(0.0f, 0.0f, 0.0f, 0.0f);
    const bool hasL = (t > 0);
    const bool hasR = (t < NT - 1);

    // Issue one row into ring slot (gi - i0 + 1) & 7. cp.async.cg when in
    // range, STS zeros otherwise; always commits a group (static wait counts).
    auto issue = [&](int gi) {
        const int slot = (gi - i0 + 1) & (NSLOT - 1);
        if ((unsigned)gi < (unsigned)H) {
            const float* src = xb + (size_t)gi * ROWW + t * 4;
            const uint32_t dst = ring_smem + slot * (ROWW * 4);
            asm volatile("cp.async.cg.shared.global [%0], [%1], 16;\n"
                         :: "r"(dst), "l"(src));
        } else {
            reinterpret_cast<float4*>(ring[slot] + t * 4)[0] = Z;
        }
        asm volatile("cp.async.commit_group;\n");
    };

    // Horizontal pass on the row in `slot`: h[e] = a*(x[e-3]+x[e+3]) + x[e].
    auto hrow = [&](int slot) -> float4 {
        const float4* rp4 = reinterpret_cast<const float4*>(ring[slot]);
        const float4 C = rp4[t];
        const float4 L = hasL ? rp4[t - 1] : Z;
        const float4 R = hasR ? rp4[t + 1] : Z;
        float4 h;
        h.x = fmaf(a, L.y + C.w, C.x);
        h.y = fmaf(a, L.z + R.x, C.y);
        h.z = fmaf(a, L.w + R.y, C.z);
        h.w = fmaf(a, C.x + R.z, C.w);
        return h;
    };

    // Prologue: fill the ring with rows i0-1 .. i0+6 (8 groups), wait until
    // rows i0-1, i0 have landed, fence, and build hm/hc.
    issue(i0 - 1); issue(i0);     issue(i0 + 1); issue(i0 + 2);
    issue(i0 + 3); issue(i0 + 4); issue(i0 + 5); issue(i0 + 6);
    asm volatile("cp.async.wait_group 6;\n");
    __syncthreads();

    float4 hm = hrow(0);   // h(row i0-1)
    float4 hc = hrow(1);   // h(row i0)

    #pragma unroll 1
    for (int r = 0; r < RPB; r++) {
        const int gi = i0 + r;

        // row gi+1 complete (<=5 groups pending), then cross-thread fence
        asm volatile("cp.async.wait_group 5;\n");
        __syncthreads();

        const float4 hp = hrow((r + 2) & (NSLOT - 1));   // h(row gi+1)

        float4 o;
        o.x = inv * (hm.x + hc.x + hp.x);
        o.y = inv * (hm.y + hc.y + hp.y);
        o.z = inv * (hm.z + hc.z + hp.z);
        o.w = inv * (hm.w + hc.w + hp.w);

        __stcs(&reinterpret_cast<float4*>(ob + (size_t)gi * ROWW)[t], o);

        // refill the ring AFTER the barrier: slot of row gi+7 was last read
        // at iteration r-2, separated from this write by two barriers.
        issue(gi + 7);

        hm = hc; hc = hp;
    }
}

extern "C" void kernel_launch(void* const* d_in, const int* in_sizes, int n_in,
                              void* d_out, int out_size)
{
    const float* x    = (const float*)d_in[0];
    const float* stds = (const float*)d_in[1];
    float* out        = (float*)d_out;

    dim3 grid(H / RPB, 64);   // (16, 64) = 1024 blocks
    gauss_blur_kernel<<<grid, NT>>>(x, stds, out);
}